// round 13
// baseline (speedup 1.0000x reference)
#include <cuda_runtime.h>

#define CH 64
#define MMAX 50000
#define CAP 80
#define OVF_MAX 8192
#define TILE_M 16

// Allocation-free scratch.
__device__ float4 g_S4[MMAX * (CH / 4)];   // segment sums [M][64]
__device__ float  g_deg[MMAX];
__device__ int    g_cnt[MMAX];
__device__ int2   g_bin[MMAX * CAP];       // {src, __float_as_int(ew)}
__device__ int    g_ovf_n;
__device__ int2   g_ovf[OVF_MAX];          // {dst, src}
__device__ float  g_ovf_w[OVF_MAX];

#define FFMA2(acc, a, b) \
    asm("fma.rn.f32x2 %0, %1, %2, %0;" : "+l"(acc) : "l"(a), "l"(b))

__global__ void zero_kernel(int M) {
    int i = blockIdx.x * blockDim.x + threadIdx.x;
    if (i < M) g_cnt[i] = 0;
    if (i == 0) g_ovf_n = 0;
}

// Bin each edge under its destination. Packed 8B store (src + ew bits).
// Overflow (not expected at CAP=80) goes to a tiny list, applied by fixup.
__global__ void fill_kernel(const int2* __restrict__ idx2,
                            const int2* __restrict__ idx12,
                            const float2* __restrict__ ew2,
                            int E2, int E) {
    int t = blockIdx.x * blockDim.x + threadIdx.x;
    if (t >= E2) return;
    int2 ss = __ldg(&idx2[t]);
    int2 dd = __ldg(&idx12[t]);
    float2 ww = __ldg(&ew2[t]);
    int n = E - t * 2;   // handle odd tail
    #pragma unroll
    for (int j = 0; j < 2; j++) {
        if (j >= n) break;
        int src = j ? ss.y : ss.x;
        int dst = j ? dd.y : dd.x;
        float w = j ? ww.y : ww.x;
        int slot = atomicAdd(&g_cnt[dst], 1);
        if (slot < CAP) {
            g_bin[dst * CAP + slot] = make_int2(src, __float_as_int(w));
        } else {
            int o = atomicAdd(&g_ovf_n, 1);
            if (o < OVF_MAX) {
                g_ovf[o] = make_int2(dst, src);
                g_ovf_w[o] = w;
            }
        }
    }
}

// One warp per segment. Bin entries loaded with ONE coalesced int2 load per
// 32-chunk; src broadcast via shfl. Plain stores — no atomics, no pre-zero.
__global__ __launch_bounds__(256) void seg_kernel(const float2* __restrict__ A2,
                                                  int M) {
    int w = (blockIdx.x * blockDim.x + threadIdx.x) >> 5;
    int l = threadIdx.x & 31;
    if (w >= M) return;
    int cnt = g_cnt[w];
    if (cnt > CAP) cnt = CAP;

    float ax = 0.f, ay = 0.f, dl = 0.f;
    for (int c0 = 0; c0 < cnt; c0 += 32) {
        int nn = cnt - c0; if (nn > 32) nn = 32;
        int2 b = (l < nn) ? __ldg(&g_bin[w * CAP + c0 + l]) : make_int2(0, 0);
        if (l < nn) dl += __int_as_float(b.y);
        for (int j = 0; j < nn; j++) {
            int src = __shfl_sync(0xffffffffu, b.x, j);
            float2 v = __ldg(&A2[src * 32 + l]);
            ax += v.x; ay += v.y;
        }
    }
    #pragma unroll
    for (int o = 16; o; o >>= 1) dl += __shfl_xor_sync(0xffffffffu, dl, o);

    ((float2*)g_S4)[w * 32 + l] = make_float2(ax, ay);
    if (l == 0) g_deg[w] = dl;
}

// Apply overflow edges (normally zero of them) on top of seg's stores.
__global__ void fixup_kernel(const float4* __restrict__ A4) {
    int n = g_ovf_n;
    if (n > OVF_MAX) n = OVF_MAX;
    for (int t = threadIdx.x; t < n * 16; t += blockDim.x) {
        int e = t >> 4, q = t & 15;
        int2 ds = g_ovf[e];
        float4 v = __ldg(&A4[ds.y * 16 + q]);
        float4* p = &g_S4[ds.x * 16 + q];
        asm volatile("red.global.add.v4.f32 [%0], {%1,%2,%3,%4};"
                     :: "l"(p), "f"(v.x), "f"(v.y), "f"(v.z), "f"(v.w)
                     : "memory");
        if (q == 0) atomicAdd(&g_deg[ds.x], g_ovf_w[e]);
    }
}

// Epilogue. TILE_M=16 keeps smem at exactly 56KB (48KB weights + 2x4KB X/S)
// so 4 blocks/SM fit -> 32 resident warps (was 24). Each thread: 1 col x 4
// rows, FFMA2 loop body identical to the proven kernel. deg read via __ldg.
__global__ __launch_bounds__(256, 4) void final_kernel(
        const float4* __restrict__ A4,
        const int* __restrict__ vn,
        const float* __restrict__ W1,
        const float* __restrict__ b1,
        const float* __restrict__ W2,
        const float* __restrict__ b2,
        const float* __restrict__ Wt,   // weight, layout [k][c]
        float* __restrict__ out,
        int M, int numTiles) {
    extern __shared__ float4 sm[];
    float4* sW1v = sm;                   // [16][64]: kk -> W1[c][4kk..4kk+3]
    float4* sW2v = sm + 1024;            // [16][64]
    float4* sWv  = sm + 2048;            // [16][64]: kk -> Wt[4kk..4kk+3][c]
    float4* sX   = sm + 3072;            // [16][16]
    float4* sS   = sm + 3328;            // [16][16]

    int tid = threadIdx.x;
    int c = tid & 63;
    int g = tid >> 6;
    float b1c = __ldg(&b1[c]);
    float b2c = __ldg(&b2[c]);

    const float4* W1v4 = (const float4*)W1;
    const float4* W2v4 = (const float4*)W2;
    for (int i = tid; i < 1024; i += 256) {
        int kk = i >> 6, cc = i & 63;
        sW1v[i] = __ldg(&W1v4[cc * 16 + kk]);
        sW2v[i] = __ldg(&W2v4[cc * 16 + kk]);
        int k0 = kk * 4;
        sWv[i] = make_float4(__ldg(&Wt[(k0 + 0) * CH + cc]),
                             __ldg(&Wt[(k0 + 1) * CH + cc]),
                             __ldg(&Wt[(k0 + 2) * CH + cc]),
                             __ldg(&Wt[(k0 + 3) * CH + cc]));
    }

    for (int tile = blockIdx.x; tile < numTiles; tile += gridDim.x) {
        int m0 = tile * TILE_M;
        __syncthreads();
        {   // stage 16 rows x 16 float4 = 256 entries: exactly 1 per thread
            int r = tid >> 4, q = tid & 15;
            int m = m0 + r;
            int mc = (m < M) ? m : 0;
            int rowA = (m < M) ? vn[m] : 0;
            sX[tid] = __ldg(&A4[rowA * 16 + q]);
            sS[tid] = g_S4[mc * 16 + q];
        }
        __syncthreads();

        unsigned long long a1[4], a2[4], a3[4];
        #pragma unroll
        for (int r = 0; r < 4; r++) { a1[r] = 0ull; a2[r] = 0ull; a3[r] = 0ull; }

        #pragma unroll
        for (int kk = 0; kk < 16; kk++) {
            ulonglong2 w1 = *(const ulonglong2*)&sW1v[kk * 64 + c];
            ulonglong2 w2 = *(const ulonglong2*)&sW2v[kk * 64 + c];
            ulonglong2 wv = *(const ulonglong2*)&sWv [kk * 64 + c];
            #pragma unroll
            for (int r = 0; r < 4; r++) {
                ulonglong2 x = *(const ulonglong2*)&sX[(g * 4 + r) * 16 + kk];
                ulonglong2 s = *(const ulonglong2*)&sS[(g * 4 + r) * 16 + kk];
                FFMA2(a1[r], x.x, w1.x); FFMA2(a1[r], x.y, w1.y);
                FFMA2(a2[r], x.x, w2.x); FFMA2(a2[r], x.y, w2.y);
                FFMA2(a3[r], s.x, wv.x); FFMA2(a3[r], s.y, wv.y);
            }
        }

        #pragma unroll
        for (int r = 0; r < 4; r++) {
            int m = m0 + g * 4 + r;
            if (m < M) {
                unsigned lo, hi;
                float s1, s2, s3;
                asm("mov.b64 {%0,%1}, %2;" : "=r"(lo), "=r"(hi) : "l"(a1[r]));
                s1 = __uint_as_float(lo) + __uint_as_float(hi);
                asm("mov.b64 {%0,%1}, %2;" : "=r"(lo), "=r"(hi) : "l"(a2[r]));
                s2 = __uint_as_float(lo) + __uint_as_float(hi);
                asm("mov.b64 {%0,%1}, %2;" : "=r"(lo), "=r"(hi) : "l"(a3[r]));
                s3 = __uint_as_float(lo) + __uint_as_float(hi);
                float d = __ldg(&g_deg[m]);
                out[m * CH + c] = d * (s1 + b1c) + s3 + s2 + b2c;
            }
        }
    }
}

extern "C" void kernel_launch(void* const* d_in, const int* in_sizes, int n_in,
                              void* d_out, int out_size) {
    const float* A    = (const float*)d_in[0];   // [N, 64] f32
    const int*   vn   = (const int*)d_in[1];     // [M] int32
    const int*   idx  = (const int*)d_in[2];     // [E] int32
    const int*   idx1 = (const int*)d_in[3];     // [E] int32
    const float* ew   = (const float*)d_in[4];   // [E] f32
    const float* Wt   = (const float*)d_in[5];   // [64, 64] = [CIN][COUT]
    const float* W1   = (const float*)d_in[6];   // [64, 64] = [COUT][CIN]
    const float* b1   = (const float*)d_in[7];   // [64]
    const float* W2   = (const float*)d_in[8];   // [64, 64]
    const float* b2   = (const float*)d_in[9];   // [64]
    float* out = (float*)d_out;

    int M = in_sizes[1];
    int E = in_sizes[2];

    zero_kernel<<<(M + 255) / 256, 256>>>(M);
    {
        int E2 = (E + 1) / 2;
        fill_kernel<<<(E2 + 255) / 256, 256>>>(
            (const int2*)idx, (const int2*)idx1, (const float2*)ew, E2, E);
    }
    {
        int blocks = (M * 32 + 255) / 256;
        seg_kernel<<<blocks, 256>>>((const float2*)A, M);
    }
    fixup_kernel<<<1, 256>>>((const float4*)A);
    {
        int smemBytes = 3584 * sizeof(float4);   // 57344 = 56KB exactly
        cudaFuncSetAttribute(final_kernel,
                             cudaFuncAttributeMaxDynamicSharedMemorySize,
                             smemBytes);
        int numTiles = (M + TILE_M - 1) / TILE_M;
        int blocks = 592;                         // 4 blocks/SM target
        if (blocks > numTiles) blocks = numTiles;
        final_kernel<<<blocks, 256, smemBytes>>>(
            (const float4*)A, vn, W1, b1, W2, b2, Wt, out, M, numTiles);
    }
}

// round 15
// speedup vs baseline: 1.0145x; 1.0145x over previous
#include <cuda_runtime.h>

#define CH 64
#define MMAX 50000
#define CAP 80
#define OVF_MAX 8192
#define TILE_M 16

// Allocation-free scratch.
__device__ float4 g_S4[MMAX * (CH / 4)];   // segment sums [M][64]
__device__ float  g_deg[MMAX];
__device__ int    g_cnt[MMAX];
__device__ int2   g_bin[MMAX * CAP];       // {src, __float_as_int(ew)}
__device__ int    g_ovf_n;
__device__ int2   g_ovf[OVF_MAX];          // {dst, src}
__device__ float  g_ovf_w[OVF_MAX];

#define FFMA2(acc, a, b) \
    asm("fma.rn.f32x2 %0, %1, %2, %0;" : "+l"(acc) : "l"(a), "l"(b))

__global__ void zero_kernel(int M) {
    int i = blockIdx.x * blockDim.x + threadIdx.x;
    if (i < M) g_cnt[i] = 0;
    if (i == 0) g_ovf_n = 0;
}

// Bin each edge under its destination. Packed 8B store (src + ew bits).
// Overflow (not expected at CAP=80) goes to a tiny list, applied by fixup.
__global__ void fill_kernel(const int2* __restrict__ idx2,
                            const int2* __restrict__ idx12,
                            const float2* __restrict__ ew2,
                            int E2, int E) {
    int t = blockIdx.x * blockDim.x + threadIdx.x;
    if (t >= E2) return;
    int2 ss = __ldg(&idx2[t]);
    int2 dd = __ldg(&idx12[t]);
    float2 ww = __ldg(&ew2[t]);
    int n = E - t * 2;   // handle odd tail
    #pragma unroll
    for (int j = 0; j < 2; j++) {
        if (j >= n) break;
        int src = j ? ss.y : ss.x;
        int dst = j ? dd.y : dd.x;
        float w = j ? ww.y : ww.x;
        int slot = atomicAdd(&g_cnt[dst], 1);
        if (slot < CAP) {
            g_bin[dst * CAP + slot] = make_int2(src, __float_as_int(w));
        } else {
            int o = atomicAdd(&g_ovf_n, 1);
            if (o < OVF_MAX) {
                g_ovf[o] = make_int2(dst, src);
                g_ovf_w[o] = w;
            }
        }
    }
}

// One warp per segment. Bin entries loaded with ONE coalesced int2 load per
// 32-chunk; src broadcast via shfl. Plain stores — no atomics, no pre-zero.
__global__ __launch_bounds__(256) void seg_kernel(const float2* __restrict__ A2,
                                                  int M) {
    int w = (blockIdx.x * blockDim.x + threadIdx.x) >> 5;
    int l = threadIdx.x & 31;
    if (w >= M) return;
    int cnt = g_cnt[w];
    if (cnt > CAP) cnt = CAP;

    float ax = 0.f, ay = 0.f, dl = 0.f;
    for (int c0 = 0; c0 < cnt; c0 += 32) {
        int nn = cnt - c0; if (nn > 32) nn = 32;
        int2 b = (l < nn) ? __ldg(&g_bin[w * CAP + c0 + l]) : make_int2(0, 0);
        if (l < nn) dl += __int_as_float(b.y);
        for (int j = 0; j < nn; j++) {
            int src = __shfl_sync(0xffffffffu, b.x, j);
            float2 v = __ldg(&A2[src * 32 + l]);
            ax += v.x; ay += v.y;
        }
    }
    #pragma unroll
    for (int o = 16; o; o >>= 1) dl += __shfl_xor_sync(0xffffffffu, dl, o);

    ((float2*)g_S4)[w * 32 + l] = make_float2(ax, ay);
    if (l == 0) g_deg[w] = dl;
}

// Apply overflow edges (normally zero of them) on top of seg's stores.
__global__ void fixup_kernel(const float4* __restrict__ A4) {
    int n = g_ovf_n;
    if (n > OVF_MAX) n = OVF_MAX;
    for (int t = threadIdx.x; t < n * 16; t += blockDim.x) {
        int e = t >> 4, q = t & 15;
        int2 ds = g_ovf[e];
        float4 v = __ldg(&A4[ds.y * 16 + q]);
        float4* p = &g_S4[ds.x * 16 + q];
        asm volatile("red.global.add.v4.f32 [%0], {%1,%2,%3,%4};"
                     :: "l"(p), "f"(v.x), "f"(v.y), "f"(v.z), "f"(v.w)
                     : "memory");
        if (q == 0) atomicAdd(&g_deg[ds.x], g_ovf_w[e]);
    }
}

// Epilogue. TILE_M=16 keeps smem at exactly 56KB (48KB weights + 2x4KB X/S)
// so 4 blocks/SM fit -> 32 resident warps (was 24). Each thread: 1 col x 4
// rows, FFMA2 loop body identical to the proven kernel. deg read via __ldg.
__global__ __launch_bounds__(256, 4) void final_kernel(
        const float4* __restrict__ A4,
        const int* __restrict__ vn,
        const float* __restrict__ W1,
        const float* __restrict__ b1,
        const float* __restrict__ W2,
        const float* __restrict__ b2,
        const float* __restrict__ Wt,   // weight, layout [k][c]
        float* __restrict__ out,
        int M, int numTiles) {
    extern __shared__ float4 sm[];
    float4* sW1v = sm;                   // [16][64]: kk -> W1[c][4kk..4kk+3]
    float4* sW2v = sm + 1024;            // [16][64]
    float4* sWv  = sm + 2048;            // [16][64]: kk -> Wt[4kk..4kk+3][c]
    float4* sX   = sm + 3072;            // [16][16]
    float4* sS   = sm + 3328;            // [16][16]

    int tid = threadIdx.x;
    int c = tid & 63;
    int g = tid >> 6;
    float b1c = __ldg(&b1[c]);
    float b2c = __ldg(&b2[c]);

    const float4* W1v4 = (const float4*)W1;
    const float4* W2v4 = (const float4*)W2;
    for (int i = tid; i < 1024; i += 256) {
        int kk = i >> 6, cc = i & 63;
        sW1v[i] = __ldg(&W1v4[cc * 16 + kk]);
        sW2v[i] = __ldg(&W2v4[cc * 16 + kk]);
        int k0 = kk * 4;
        sWv[i] = make_float4(__ldg(&Wt[(k0 + 0) * CH + cc]),
                             __ldg(&Wt[(k0 + 1) * CH + cc]),
                             __ldg(&Wt[(k0 + 2) * CH + cc]),
                             __ldg(&Wt[(k0 + 3) * CH + cc]));
    }

    for (int tile = blockIdx.x; tile < numTiles; tile += gridDim.x) {
        int m0 = tile * TILE_M;
        __syncthreads();
        {   // stage 16 rows x 16 float4 = 256 entries: exactly 1 per thread
            int r = tid >> 4, q = tid & 15;
            int m = m0 + r;
            int mc = (m < M) ? m : 0;
            int rowA = (m < M) ? vn[m] : 0;
            sX[tid] = __ldg(&A4[rowA * 16 + q]);
            sS[tid] = g_S4[mc * 16 + q];
        }
        __syncthreads();

        unsigned long long a1[4], a2[4], a3[4];
        #pragma unroll
        for (int r = 0; r < 4; r++) { a1[r] = 0ull; a2[r] = 0ull; a3[r] = 0ull; }

        #pragma unroll
        for (int kk = 0; kk < 16; kk++) {
            ulonglong2 w1 = *(const ulonglong2*)&sW1v[kk * 64 + c];
            ulonglong2 w2 = *(const ulonglong2*)&sW2v[kk * 64 + c];
            ulonglong2 wv = *(const ulonglong2*)&sWv [kk * 64 + c];
            #pragma unroll
            for (int r = 0; r < 4; r++) {
                ulonglong2 x = *(const ulonglong2*)&sX[(g * 4 + r) * 16 + kk];
                ulonglong2 s = *(const ulonglong2*)&sS[(g * 4 + r) * 16 + kk];
                FFMA2(a1[r], x.x, w1.x); FFMA2(a1[r], x.y, w1.y);
                FFMA2(a2[r], x.x, w2.x); FFMA2(a2[r], x.y, w2.y);
                FFMA2(a3[r], s.x, wv.x); FFMA2(a3[r], s.y, wv.y);
            }
        }

        #pragma unroll
        for (int r = 0; r < 4; r++) {
            int m = m0 + g * 4 + r;
            if (m < M) {
                unsigned lo, hi;
                float s1, s2, s3;
                asm("mov.b64 {%0,%1}, %2;" : "=r"(lo), "=r"(hi) : "l"(a1[r]));
                s1 = __uint_as_float(lo) + __uint_as_float(hi);
                asm("mov.b64 {%0,%1}, %2;" : "=r"(lo), "=r"(hi) : "l"(a2[r]));
                s2 = __uint_as_float(lo) + __uint_as_float(hi);
                asm("mov.b64 {%0,%1}, %2;" : "=r"(lo), "=r"(hi) : "l"(a3[r]));
                s3 = __uint_as_float(lo) + __uint_as_float(hi);
                float d = __ldg(&g_deg[m]);
                out[m * CH + c] = d * (s1 + b1c) + s3 + s2 + b2c;
            }
        }
    }
}

extern "C" void kernel_launch(void* const* d_in, const int* in_sizes, int n_in,
                              void* d_out, int out_size) {
    const float* A    = (const float*)d_in[0];   // [N, 64] f32
    const int*   vn   = (const int*)d_in[1];     // [M] int32
    const int*   idx  = (const int*)d_in[2];     // [E] int32
    const int*   idx1 = (const int*)d_in[3];     // [E] int32
    const float* ew   = (const float*)d_in[4];   // [E] f32
    const float* Wt   = (const float*)d_in[5];   // [64, 64] = [CIN][COUT]
    const float* W1   = (const float*)d_in[6];   // [64, 64] = [COUT][CIN]
    const float* b1   = (const float*)d_in[7];   // [64]
    const float* W2   = (const float*)d_in[8];   // [64, 64]
    const float* b2   = (const float*)d_in[9];   // [64]
    float* out = (float*)d_out;

    int M = in_sizes[1];
    int E = in_sizes[2];

    zero_kernel<<<(M + 255) / 256, 256>>>(M);
    {
        int E2 = (E + 1) / 2;
        fill_kernel<<<(E2 + 255) / 256, 256>>>(
            (const int2*)idx, (const int2*)idx1, (const float2*)ew, E2, E);
    }
    {
        int blocks = (M * 32 + 255) / 256;
        seg_kernel<<<blocks, 256>>>((const float2*)A, M);
    }
    fixup_kernel<<<1, 256>>>((const float4*)A);
    {
        int smemBytes = 3584 * sizeof(float4);   // 57344 = 56KB exactly
        cudaFuncSetAttribute(final_kernel,
                             cudaFuncAttributeMaxDynamicSharedMemorySize,
                             smemBytes);
        int numTiles = (M + TILE_M - 1) / TILE_M;
        int blocks = 592;                         // 4 blocks/SM target
        if (blocks > numTiles) blocks = numTiles;
        final_kernel<<<blocks, 256, smemBytes>>>(
            (const float4*)A, vn, W1, b1, W2, b2, Wt, out, M, numTiles);
    }
}